// round 14
// baseline (speedup 1.0000x reference)
#include <cuda_runtime.h>
#include <cuda_bf16.h>
#include <math.h>
#include <stdint.h>

#define S_LEN 512
#define B_SZ  64
#define HID   1024
#define G4    4096
#define NACT  128
#define NBLK  128
#define UPB   8
#define VOCAB 32000

// ---------------- scratch ----------------------------------------------------
__device__ float g_gx[(size_t)S_LEN * B_SZ * G4];   // [s][b][4H]
__device__ float g_hs[(size_t)B_SZ * S_LEN * HID];  // [b][s][H]
// h (hi only) in m16n8k16 A-fragment layout: [buf][rt(4)][ct(64)][lane(32)] uint4
__device__ uint4 g_hfrag[2][4 * 64 * 32];
__device__ __nv_bfloat16 g_embH[(size_t)VOCAB * HID];
__device__ __nv_bfloat16 g_embL[(size_t)VOCAB * HID];
__device__ __nv_bfloat16 g_WiH[(size_t)HID * G4];
__device__ __nv_bfloat16 g_WiL[(size_t)HID * G4];
__device__ unsigned g_arrive;
__device__ unsigned g_release;

// ---------------- helpers ----------------------------------------------------
__device__ __forceinline__ uint32_t smem_u32(const void* p) {
    return (uint32_t)__cvta_generic_to_shared(p);
}
__device__ __forceinline__ void ldsm_x4(uint32_t a, uint32_t& r0, uint32_t& r1,
                                        uint32_t& r2, uint32_t& r3) {
    asm volatile("ldmatrix.sync.aligned.m8n8.x4.shared.b16 {%0,%1,%2,%3}, [%4];"
                 : "=r"(r0), "=r"(r1), "=r"(r2), "=r"(r3) : "r"(a));
}
__device__ __forceinline__ void ldsm_x4t(uint32_t a, uint32_t& r0, uint32_t& r1,
                                         uint32_t& r2, uint32_t& r3) {
    asm volatile("ldmatrix.sync.aligned.m8n8.x4.trans.shared.b16 {%0,%1,%2,%3}, [%4];"
                 : "=r"(r0), "=r"(r1), "=r"(r2), "=r"(r3) : "r"(a));
}
__device__ __forceinline__ void mma16816(float* c, const uint32_t* a, const uint32_t* b) {
    asm volatile("mma.sync.aligned.m16n8k16.row.col.f32.bf16.bf16.f32 "
                 "{%0,%1,%2,%3},{%4,%5,%6,%7},{%8,%9},{%0,%1,%2,%3};"
                 : "+f"(c[0]), "+f"(c[1]), "+f"(c[2]), "+f"(c[3])
                 : "r"(a[0]), "r"(a[1]), "r"(a[2]), "r"(a[3]), "r"(b[0]), "r"(b[1]));
}
__device__ __forceinline__ uint32_t packbf(__nv_bfloat16 lo, __nv_bfloat16 hi) {
    return (uint32_t)__bfloat16_as_ushort(lo) | ((uint32_t)__bfloat16_as_ushort(hi) << 16);
}
__device__ __forceinline__ void split4(float4 v, uint32_t& h0, uint32_t& h1,
                                       uint32_t& l0, uint32_t& l1) {
    __nv_bfloat16 a = __float2bfloat16(v.x), b = __float2bfloat16(v.y);
    __nv_bfloat16 c = __float2bfloat16(v.z), d = __float2bfloat16(v.w);
    __nv_bfloat16 ra = __float2bfloat16(v.x - __bfloat162float(a));
    __nv_bfloat16 rb = __float2bfloat16(v.y - __bfloat162float(b));
    __nv_bfloat16 rc = __float2bfloat16(v.z - __bfloat162float(c));
    __nv_bfloat16 rd = __float2bfloat16(v.w - __bfloat162float(d));
    h0 = packbf(a, b); h1 = packbf(c, d);
    l0 = packbf(ra, rb); l1 = packbf(rc, rd);
}
#define CP_ASYNC16(dst, src) \
    asm volatile("cp.async.cg.shared.global [%0], [%1], 16;" :: "r"(dst), "l"(src))
#define CP_COMMIT() asm volatile("cp.async.commit_group;" ::: "memory")
#define CP_WAIT0()  asm volatile("cp.async.wait_group 0;" ::: "memory")

// ---------------- init -------------------------------------------------------
__global__ void init_kernel(float* __restrict__ out, int has_dummy) {
    int i = blockIdx.x * 256 + threadIdx.x;          // 65536 threads
    if (i < 4 * 64 * 32)
        g_hfrag[0][i] = make_uint4(0u, 0u, 0u, 0u);
    if (i == 0) { g_arrive = 0u; g_release = 0u; }
    if (has_dummy && i < 2 * B_SZ * S_LEN) {
        int off = (i < B_SZ * S_LEN) ? i : (B_SZ * S_LEN * NACT + i);
        out[off] = 0.f;
    }
}

// ---------------- prep: split fp32 -> bf16 hi/lo (once) ----------------------
__global__ __launch_bounds__(256) void prep_split(const float* __restrict__ src,
                                                  __nv_bfloat16* __restrict__ hi,
                                                  __nv_bfloat16* __restrict__ lo) {
    size_t i = ((size_t)blockIdx.x * 256 + threadIdx.x) * 4;
    float4 v = *(const float4*)&src[i];
    uint32_t h0, h1, l0, l1; split4(v, h0, h1, l0, l1);
    *(uint2*)&hi[i] = make_uint2(h0, h1);
    *(uint2*)&lo[i] = make_uint2(l0, l1);
}

// ---------------- phase 1: gx = embed[x] @ Wi (cp.async double-buffered) -----
#define ASTR 40
#define BSTR 136
// dyn smem (ushorts): AsH[2][128][40] | AsL[2][128][40] | BsH[2][32][136] | BsL[2][32][136]
#define GX_A_BUF   (128 * ASTR)
#define GX_B_BUF   (32 * BSTR)
#define GX_OFF_ASL (2 * GX_A_BUF)
#define GX_OFF_BSH (4 * GX_A_BUF)
#define GX_OFF_BSL (4 * GX_A_BUF + 2 * GX_B_BUF)
#define GX_SMEM    ((4 * GX_A_BUF + 4 * GX_B_BUF) * 2)   // bytes = 75776

__global__ __launch_bounds__(256) void gemm_gx(const int* __restrict__ x) {
    extern __shared__ __align__(16) unsigned short dynsm[];
    __shared__ int rows[128];

    const int bn = blockIdx.x * 128;
    const int bm = blockIdx.y * 128;
    const int t  = threadIdx.x;
    const int lane = t & 31;
    const int w  = t >> 5;
    const int wm = (w >> 2) * 64;
    const int wn = (w & 3) * 32;

    if (t < 128) {
        int m = bm + t;
        rows[t] = x[(m & 63) * S_LEN + (m >> 6)] * HID;
    }
    __syncthreads();

    float acc[4][4][4];
#pragma unroll
    for (int i = 0; i < 4; i++)
#pragma unroll
        for (int j = 0; j < 4; j++)
#pragma unroll
            for (int k = 0; k < 4; k++) acc[i][j][k] = 0.f;

    const int ar = t >> 1, ak = (t & 1) * 16;
    const int bk = t >> 3, bn0 = (t & 7) * 16;

    // staging helper addresses (ushort indices)
    auto stage = [&](int k0, int buf) {
        size_t aoff = (size_t)rows[ar] + k0 + ak;
        uint32_t aH = smem_u32(&dynsm[buf * GX_A_BUF + ar * ASTR + ak]);
        uint32_t aL = smem_u32(&dynsm[GX_OFF_ASL + buf * GX_A_BUF + ar * ASTR + ak]);
        CP_ASYNC16(aH,      &g_embH[aoff]);
        CP_ASYNC16(aH + 16, &g_embH[aoff + 8]);
        CP_ASYNC16(aL,      &g_embL[aoff]);
        CP_ASYNC16(aL + 16, &g_embL[aoff + 8]);
        size_t boff = (size_t)(k0 + bk) * G4 + bn + bn0;
        uint32_t bH = smem_u32(&dynsm[GX_OFF_BSH + buf * GX_B_BUF + bk * BSTR + bn0]);
        uint32_t bL = smem_u32(&dynsm[GX_OFF_BSL + buf * GX_B_BUF + bk * BSTR + bn0]);
        CP_ASYNC16(bH,      &g_WiH[boff]);
        CP_ASYNC16(bH + 16, &g_WiH[boff + 8]);
        CP_ASYNC16(bL,      &g_WiL[boff]);
        CP_ASYNC16(bL + 16, &g_WiL[boff + 8]);
    };

    stage(0, 0);
    CP_COMMIT();
    CP_WAIT0();
    __syncthreads();

    for (int k0 = 0; k0 < HID; k0 += 32) {
        const int buf = (k0 >> 5) & 1;
        if (k0 + 32 < HID) {
            stage(k0 + 32, buf ^ 1);
            CP_COMMIT();
        }
        const unsigned short* AsH = &dynsm[buf * GX_A_BUF];
        const unsigned short* AsL = &dynsm[GX_OFF_ASL + buf * GX_A_BUF];
        const unsigned short* BsH = &dynsm[GX_OFF_BSH + buf * GX_B_BUF];
        const unsigned short* BsL = &dynsm[GX_OFF_BSL + buf * GX_B_BUF];

#pragma unroll
        for (int k16 = 0; k16 < 2; k16++) {
            uint32_t bH[4][2], bL[4][2];
#pragma unroll
            for (int p = 0; p < 2; p++) {
                int krow = k16 * 16 + (lane & 15);
                int ncol = wn + p * 16 + (lane >> 4) * 8;
                uint32_t r0, r1, r2, r3;
                ldsm_x4t(smem_u32(&BsH[krow * BSTR + ncol]), r0, r1, r2, r3);
                bH[p * 2][0] = r0; bH[p * 2][1] = r1;
                bH[p * 2 + 1][0] = r2; bH[p * 2 + 1][1] = r3;
                ldsm_x4t(smem_u32(&BsL[krow * BSTR + ncol]), r0, r1, r2, r3);
                bL[p * 2][0] = r0; bL[p * 2][1] = r1;
                bL[p * 2 + 1][0] = r2; bL[p * 2 + 1][1] = r3;
            }
#pragma unroll
            for (int mf = 0; mf < 4; mf++) {
                int arow = wm + mf * 16 + (lane & 15);
                int acol = k16 * 16 + (lane >> 4) * 8;
                uint32_t aH[4], aL[4];
                ldsm_x4(smem_u32(&AsH[arow * ASTR + acol]), aH[0], aH[1], aH[2], aH[3]);
                ldsm_x4(smem_u32(&AsL[arow * ASTR + acol]), aL[0], aL[1], aL[2], aL[3]);
#pragma unroll
                for (int nf = 0; nf < 4; nf++) {
                    mma16816(acc[mf][nf], aH, bH[nf]);
                    mma16816(acc[mf][nf], aH, bL[nf]);
                    mma16816(acc[mf][nf], aL, bH[nf]);
                }
            }
        }
        if (k0 + 32 < HID) CP_WAIT0();
        __syncthreads();
    }
#pragma unroll
    for (int mf = 0; mf < 4; mf++) {
        int gm = bm + wm + mf * 16 + (lane >> 2);
#pragma unroll
        for (int nf = 0; nf < 4; nf++) {
            int gn = bn + wn + nf * 8 + 2 * (lane & 3);
            *(float2*)&g_gx[(size_t)gm * G4 + gn] =
                make_float2(acc[mf][nf][0], acc[mf][nf][1]);
            *(float2*)&g_gx[(size_t)(gm + 8) * G4 + gn] =
                make_float2(acc[mf][nf][2], acc[mf][nf][3]);
        }
    }
}

// ---------------- grid barrier (flat, proven) --------------------------------
__device__ __forceinline__ void grid_barrier(unsigned epoch) {
    __syncthreads();
    if (threadIdx.x == 0) {
        __threadfence();
        unsigned prev = atomicAdd(&g_arrive, 1u);
        if (prev + 1u == (unsigned)NBLK * epoch) {
            atomicExch(&g_release, epoch);
        } else {
            unsigned r;
            do {
                asm volatile("ld.acquire.gpu.u32 %0, [%1];"
                             : "=r"(r) : "l"(&g_release) : "memory");
            } while (r < epoch);
        }
    }
    __syncthreads();
}

// ---------------- persistent scan: hi-only h fragments (R13 verbatim) --------
#define WHF_BYTES 131072
#define GSM_STR 34
#define SCAN_SMEM (WHF_BYTES + 34816)

__global__ __launch_bounds__(256, 1) void scan_kernel(const float* __restrict__ Wh,
                                                      const float* __restrict__ bh) {
    extern __shared__ char smraw[];
    uint4* WhF = (uint4*)smraw;                                   // [64][4][32]
    float* gsm = (float*)(smraw + WHF_BYTES);                     // [4][64][34]
    __shared__ float bsm[4][UPB];
    __shared__ float csm[64][UPB];

    const int t = threadIdx.x, lane = t & 31, w = t >> 5;
    const int mg = w & 1, ks = w >> 1;        // 2 m-groups x 4 k-splits
    const int j0 = blockIdx.x * UPB;

    // ---- preload Wh slice into fragment-ordered SMEM (once); temp in gsm ----
    __nv_bfloat16* tileH = (__nv_bfloat16*)gsm;         // [128][40]
    __nv_bfloat16* tileL = tileH + 128 * 40;
    for (int kc = 0; kc < 8; kc++) {
        __syncthreads();
#pragma unroll
        for (int i = 0; i < 16; i++) {
            int idx = i * 256 + t;
            int kl = idx >> 5, cc = idx & 31;
            float v = Wh[(size_t)(kc * 128 + kl) * G4 + (cc >> 3) * HID + j0 + (cc & 7)];
            __nv_bfloat16 hi = __float2bfloat16(v);
            __nv_bfloat16 lo = __float2bfloat16(v - __bfloat162float(hi));
            tileH[kl * 40 + cc] = hi;
            tileL[kl * 40 + cc] = lo;
        }
        __syncthreads();
        {
            int krow = w * 16 + (lane & 15);
#pragma unroll
            for (int p = 0; p < 2; p++) {
                int ncol = p * 16 + (lane >> 4) * 8;
                uint32_t h0, h1, h2, h3, l0, l1, l2, l3;
                ldsm_x4t(smem_u32(&tileH[krow * 40 + ncol]), h0, h1, h2, h3);
                ldsm_x4t(smem_u32(&tileL[krow * 40 + ncol]), l0, l1, l2, l3);
                WhF[((kc * 8 + w) * 4 + p * 2 + 0) * 32 + lane] = make_uint4(h0, h1, l0, l1);
                WhF[((kc * 8 + w) * 4 + p * 2 + 1) * 32 + lane] = make_uint4(h2, h3, l2, l3);
            }
        }
    }
    if (t < 32) bsm[t >> 3][t & 7] = bh[(t >> 3) * HID + j0 + (t & 7)];
    for (int e = t; e < 512; e += 256) csm[e >> 3][e & 7] = 0.f;
    grid_barrier(1u);

    // pointwise fragment-store indices
    const int pw_u  = t & 7;
    const int pw_j  = j0 + pw_u;
    const int pw_ct = pw_j >> 4;
    const int pw_ci = pw_j & 15;

    // ---- 512 steps ----
    for (int s = 0; s < S_LEN; ++s) {
        float gxv[2][4];
#pragma unroll
        for (int e2 = 0; e2 < 2; e2++) {
            int e = t + e2 * 256, b = e >> 3;
            const float* gx = &g_gx[((size_t)s * B_SZ + b) * G4 + pw_j];
            gxv[e2][0] = gx[0];
            gxv[e2][1] = gx[HID];
            gxv[e2][2] = gx[2 * HID];
            gxv[e2][3] = gx[3 * HID];
        }

        float acc[2][4][4];
#pragma unroll
        for (int mi = 0; mi < 2; mi++)
#pragma unroll
            for (int g = 0; g < 4; g++)
#pragma unroll
                for (int r = 0; r < 4; r++) acc[mi][g][r] = 0.f;

        const uint4* fragR = &g_hfrag[s & 1][0];

#pragma unroll 1
        for (int c8 = 0; c8 < 8; c8++) {
#pragma unroll
            for (int kk = 0; kk < 2; kk++) {
                const int kl = c8 * 8 + ks * 2 + kk;
                uint4 aHf[2];
#pragma unroll
                for (int mi = 0; mi < 2; mi++) {
                    int rt = 2 * mg + mi;
                    aHf[mi] = fragR[((size_t)rt * 64 + kl) * 32 + lane];
                }
                uint32_t bhf[4][2], blf[4][2];
#pragma unroll
                for (int g = 0; g < 4; g++) {
                    uint4 f = WhF[((size_t)kl * 4 + g) * 32 + lane];
                    bhf[g][0] = f.x; bhf[g][1] = f.y;
                    blf[g][0] = f.z; blf[g][1] = f.w;
                }
#pragma unroll
                for (int mi = 0; mi < 2; mi++) {
                    uint32_t aH[4] = { aHf[mi].x, aHf[mi].y, aHf[mi].z, aHf[mi].w };
#pragma unroll
                    for (int g = 0; g < 4; g++) {
                        mma16816(acc[mi][g], aH, bhf[g]);
                        mma16816(acc[mi][g], aH, blf[g]);
                    }
                }
            }
        }
        __syncthreads();   // gsm free
#pragma unroll
        for (int mi = 0; mi < 2; mi++)
#pragma unroll
            for (int g = 0; g < 4; g++) {
                int m = mg * 32 + mi * 16 + (lane >> 2);
                int n = g * 8 + (lane & 3) * 2;
                *(float2*)&gsm[(ks * 64 + m) * GSM_STR + n] =
                    make_float2(acc[mi][g][0], acc[mi][g][1]);
                *(float2*)&gsm[(ks * 64 + m + 8) * GSM_STR + n] =
                    make_float2(acc[mi][g][2], acc[mi][g][3]);
            }
        __syncthreads();

        // pointwise
        unsigned short* fragW = (unsigned short*)&g_hfrag[(s + 1) & 1][0];
#pragma unroll
        for (int e2 = 0; e2 < 2; e2++) {
            int e = t + e2 * 256, b = e >> 3;
            int u = pw_u, j = pw_j;
            float gi = gxv[e2][0] + bsm[0][u];
            float gf = gxv[e2][1] + bsm[1][u];
            float gv = gxv[e2][2] + bsm[2][u];
            float go = gxv[e2][3] + bsm[3][u];
#pragma unroll
            for (int p = 0; p < 4; p++) {
                const float* gr = &gsm[(p * 64 + b) * GSM_STR];
                gi += gr[u];
                gf += gr[8 + u];
                gv += gr[16 + u];
                go += gr[24 + u];
            }
            gi = 1.f / (1.f + expf(-gi));
            gf = 1.f / (1.f + expf(-gf));
            gv = tanhf(gv);
            go = 1.f / (1.f + expf(-go));
            float c = gf * csm[b][u] + gi * gv;
            float h = go * tanhf(c);
            csm[b][u] = c;
            __nv_bfloat16 hh = __float2bfloat16(h);
            int ri = b & 15;
            int lane_w = (ri & 7) * 4 + ((pw_ci & 7) >> 1);
            int comp = ((ri >> 3) & 1) | (((pw_ci >> 3) & 1) << 1);
            size_t off16 = ((((size_t)(b >> 4) * 64 + pw_ct) * 32 + lane_w) * 4 + comp) * 2
                           + (pw_ci & 1);
            fragW[off16] = __bfloat16_as_ushort(hh);
            g_hs[((size_t)b * S_LEN + s) * HID + j] = h;
        }
        grid_barrier((unsigned)(s + 2));
    }
}

// ---------------- phase 3: logits = hs @ Wo + bo (bf16-split HMMA) -----------
__global__ __launch_bounds__(256) void gemm_logits(const float* __restrict__ Wo,
                                                   const float* __restrict__ bo,
                                                   float* __restrict__ out) {
    __shared__ __align__(16) unsigned short AsH[128][ASTR];
    __shared__ __align__(16) unsigned short AsL[128][ASTR];
    __shared__ __align__(16) unsigned short BsH[32][BSTR];
    __shared__ __align__(16) unsigned short BsL[32][BSTR];

    const int bm = blockIdx.x * 128;
    const int t  = threadIdx.x;
    const int lane = t & 31;
    const int w  = t >> 5;
    const int wm = (w >> 2) * 64;
    const int wn = (w & 3) * 32;

    float acc[4][4][4];
#pragma unroll
    for (int i = 0; i < 4; i++)
#pragma unroll
        for (int j = 0; j < 4; j++)
#pragma unroll
            for (int k = 0; k < 4; k++) acc[i][j][k] = 0.f;

    const int ar = t >> 1, ak = (t & 1) * 16;
    const int bk = t >> 3, bn0 = (t & 7) * 16;

    for (int k0 = 0; k0 < HID; k0 += 32) {
        __syncthreads();
#pragma unroll
        for (int i = 0; i < 4; i++) {
            float4 v = *(const float4*)&g_hs[(size_t)(bm + ar) * HID + k0 + ak + i * 4];
            uint32_t h0, h1, l0, l1; split4(v, h0, h1, l0, l1);
            *(uint2*)&AsH[ar][ak + i * 4] = make_uint2(h0, h1);
            *(uint2*)&AsL[ar][ak + i * 4] = make_uint2(l0, l1);
        }
        {
            uint32_t hh[8], ll[8];
#pragma unroll
            for (int i = 0; i < 4; i++) {
                float4 v = *(const float4*)&Wo[(size_t)(k0 + bk) * NACT + bn0 + i * 4];
                split4(v, hh[i * 2], hh[i * 2 + 1], ll[i * 2], ll[i * 2 + 1]);
            }
            *(uint4*)&BsH[bk][bn0]     = make_uint4(hh[0], hh[1], hh[2], hh[3]);
            *(uint4*)&BsH[bk][bn0 + 8] = make_uint4(hh[4], hh[5], hh[6], hh[7]);
            *(uint4*)&BsL[bk][bn0]     = make_uint4(ll[0], ll[1], ll[2], ll[3]);
            *(uint4*)&BsL[bk][bn0 + 8] = make_uint4(ll[4], ll[5], ll[6], ll[7]);
        }
        __syncthreads();

#pragma unroll
        for (int k16 = 0; k16 < 2; k16++) {
            uint32_t bH[4][2], bL[4][2];
#pragma unroll
            for (int p = 0; p < 2; p++) {
                int krow = k16 * 16 + (lane & 15);
                int ncol = wn + p * 16 + (lane >> 4) * 8;
                uint32_t r0, r1, r2, r3;
                ldsm_x4t(smem_u32(&BsH[krow][ncol]), r0, r1, r2, r3);
                bH[p * 2][0] = r0; bH[p * 2][1] = r1;
                bH[p * 2 + 1][0] = r2; bH[p * 2 + 1][1] = r3;
                ldsm_x4t(smem_u32(&BsL[krow][ncol]), r0, r1, r2, r3);
                bL[p * 2][0] = r0; bL[p * 2][1] = r1;
                bL[p * 2 + 1][0] = r2; bL[p * 2 + 1][1] = r3;
            }
#pragma unroll
            for (int mf = 0; mf < 4; mf++) {
                int arow = wm + mf * 16 + (lane & 15);
                int acol = k16 * 16 + (lane >> 4) * 8;
                uint32_t aH[4], aL[4];
                ldsm_x4(smem_u32(&AsH[arow][acol]), aH[0], aH[1], aH[2], aH[3]);
                ldsm_x4(smem_u32(&AsL[arow][acol]), aL[0], aL[1], aL[2], aL[3]);
#pragma unroll
                for (int nf = 0; nf < 4; nf++) {
                    mma16816(acc[mf][nf], aH, bH[nf]);
                    mma16816(acc[mf][nf], aH, bL[nf]);
                    mma16816(acc[mf][nf], aL, bH[nf]);
                }
            }
        }
    }
#pragma unroll
    for (int mf = 0; mf < 4; mf++) {
        int gm = bm + wm + mf * 16 + (lane >> 2);
#pragma unroll
        for (int nf = 0; nf < 4; nf++) {
            int gn = wn + nf * 8 + 2 * (lane & 3);
            float b0 = bo[gn], b1 = bo[gn + 1];
            *(float2*)&out[(size_t)gm * NACT + gn] =
                make_float2(acc[mf][nf][0] + b0, acc[mf][nf][1] + b1);
            *(float2*)&out[(size_t)(gm + 8) * NACT + gn] =
                make_float2(acc[mf][nf][2] + b0, acc[mf][nf][3] + b1);
        }
    }
}

// ---------------- launch -----------------------------------------------------
extern "C" void kernel_launch(void* const* d_in, const int* in_sizes, int n_in,
                              void* d_out, int out_size) {
    const float* embed = (const float*)d_in[0];
    const float* Wi    = (const float*)d_in[1];
    const float* Wh    = (const float*)d_in[2];
    const float* bh    = (const float*)d_in[3];
    const float* Wo    = (const float*)d_in[4];
    const float* bo    = (const float*)d_in[5];
    const int*   x     = (const int*)d_in[6];
    float* out = (float*)d_out;

    int has_dummy = (out_size == B_SZ * S_LEN * (NACT + 2)) ? 1 : 0;
    int logits_off = has_dummy ? B_SZ * S_LEN : 0;

    static int smem_set = 0;
    if (!smem_set) {
        cudaFuncSetAttribute(scan_kernel,
                             cudaFuncAttributeMaxDynamicSharedMemorySize, SCAN_SMEM);
        cudaFuncSetAttribute(gemm_gx,
                             cudaFuncAttributeMaxDynamicSharedMemorySize, GX_SMEM);
        smem_set = 1;
    }

    __nv_bfloat16 *eH, *eL, *wH, *wL;
    cudaGetSymbolAddress((void**)&eH, g_embH);
    cudaGetSymbolAddress((void**)&eL, g_embL);
    cudaGetSymbolAddress((void**)&wH, g_WiH);
    cudaGetSymbolAddress((void**)&wL, g_WiL);

    init_kernel<<<256, 256>>>(out, has_dummy);
    prep_split<<<(VOCAB * HID) / 1024, 256>>>(embed, eH, eL);
    prep_split<<<(HID * G4) / 1024, 256>>>(Wi, wH, wL);
    gemm_gx<<<dim3(G4 / 128, (S_LEN * B_SZ) / 128), 256, GX_SMEM>>>(x);
    scan_kernel<<<NBLK, 256, SCAN_SMEM>>>(Wh, bh);
    gemm_logits<<<(S_LEN * B_SZ) / 128, 256>>>(Wo, bo, out + logits_off);
}

// round 16
// speedup vs baseline: 1.0524x; 1.0524x over previous
#include <cuda_runtime.h>
#include <cuda_bf16.h>
#include <math.h>
#include <stdint.h>

#define S_LEN 512
#define B_SZ  64
#define HID   1024
#define G4    4096
#define NACT  128
#define NBLK  128
#define UPB   8
#define VOCAB 32000

// ---------------- scratch ----------------------------------------------------
__device__ float g_gx[(size_t)S_LEN * B_SZ * G4];   // [s][b][4H]
__device__ float g_hs[(size_t)B_SZ * S_LEN * HID];  // [b][s][H]
// h (hi only) in m16n8k16 A-fragment layout: [buf][rt(4)][ct(64)][lane(32)] uint4
__device__ uint4 g_hfrag[2][4 * 64 * 32];
__device__ __nv_bfloat16 g_embH[(size_t)VOCAB * HID];
__device__ __nv_bfloat16 g_embL[(size_t)VOCAB * HID];
__device__ __nv_bfloat16 g_WiH[(size_t)HID * G4];
__device__ __nv_bfloat16 g_WiL[(size_t)HID * G4];
__device__ unsigned g_arrive;
__device__ unsigned g_release;

// ---------------- helpers ----------------------------------------------------
__device__ __forceinline__ uint32_t smem_u32(const void* p) {
    return (uint32_t)__cvta_generic_to_shared(p);
}
__device__ __forceinline__ void ldsm_x4(uint32_t a, uint32_t& r0, uint32_t& r1,
                                        uint32_t& r2, uint32_t& r3) {
    asm volatile("ldmatrix.sync.aligned.m8n8.x4.shared.b16 {%0,%1,%2,%3}, [%4];"
                 : "=r"(r0), "=r"(r1), "=r"(r2), "=r"(r3) : "r"(a));
}
__device__ __forceinline__ void ldsm_x4t(uint32_t a, uint32_t& r0, uint32_t& r1,
                                         uint32_t& r2, uint32_t& r3) {
    asm volatile("ldmatrix.sync.aligned.m8n8.x4.trans.shared.b16 {%0,%1,%2,%3}, [%4];"
                 : "=r"(r0), "=r"(r1), "=r"(r2), "=r"(r3) : "r"(a));
}
__device__ __forceinline__ void mma16816(float* c, const uint32_t* a, const uint32_t* b) {
    asm volatile("mma.sync.aligned.m16n8k16.row.col.f32.bf16.bf16.f32 "
                 "{%0,%1,%2,%3},{%4,%5,%6,%7},{%8,%9},{%0,%1,%2,%3};"
                 : "+f"(c[0]), "+f"(c[1]), "+f"(c[2]), "+f"(c[3])
                 : "r"(a[0]), "r"(a[1]), "r"(a[2]), "r"(a[3]), "r"(b[0]), "r"(b[1]));
}
__device__ __forceinline__ uint32_t packbf(__nv_bfloat16 lo, __nv_bfloat16 hi) {
    return (uint32_t)__bfloat16_as_ushort(lo) | ((uint32_t)__bfloat16_as_ushort(hi) << 16);
}
__device__ __forceinline__ void split4(float4 v, uint32_t& h0, uint32_t& h1,
                                       uint32_t& l0, uint32_t& l1) {
    __nv_bfloat16 a = __float2bfloat16(v.x), b = __float2bfloat16(v.y);
    __nv_bfloat16 c = __float2bfloat16(v.z), d = __float2bfloat16(v.w);
    __nv_bfloat16 ra = __float2bfloat16(v.x - __bfloat162float(a));
    __nv_bfloat16 rb = __float2bfloat16(v.y - __bfloat162float(b));
    __nv_bfloat16 rc = __float2bfloat16(v.z - __bfloat162float(c));
    __nv_bfloat16 rd = __float2bfloat16(v.w - __bfloat162float(d));
    h0 = packbf(a, b); h1 = packbf(c, d);
    l0 = packbf(ra, rb); l1 = packbf(rc, rd);
}

// ---------------- init -------------------------------------------------------
__global__ void init_kernel(float* __restrict__ out, int has_dummy) {
    int i = blockIdx.x * 256 + threadIdx.x;          // 65536 threads
    if (i < 4 * 64 * 32)
        g_hfrag[0][i] = make_uint4(0u, 0u, 0u, 0u);
    if (i == 0) { g_arrive = 0u; g_release = 0u; }
    if (has_dummy && i < 2 * B_SZ * S_LEN) {
        int off = (i < B_SZ * S_LEN) ? i : (B_SZ * S_LEN * NACT + i);
        out[off] = 0.f;
    }
}

// ---------------- prep: split fp32 -> bf16 hi/lo (once) ----------------------
__global__ __launch_bounds__(256) void prep_split(const float* __restrict__ src,
                                                  __nv_bfloat16* __restrict__ hi,
                                                  __nv_bfloat16* __restrict__ lo) {
    size_t i = ((size_t)blockIdx.x * 256 + threadIdx.x) * 4;
    float4 v = *(const float4*)&src[i];
    uint32_t h0, h1, l0, l1; split4(v, h0, h1, l0, l1);
    *(uint2*)&hi[i] = make_uint2(h0, h1);
    *(uint2*)&lo[i] = make_uint2(l0, l1);
}

// ---------------- phase 1: gx = embed[x] @ Wi (R11 static form) --------------
#define ASTR 40
#define BSTR 136
__global__ __launch_bounds__(256) void gemm_gx(const int* __restrict__ x) {
    __shared__ __align__(16) unsigned short AsH[128][ASTR];
    __shared__ __align__(16) unsigned short AsL[128][ASTR];
    __shared__ __align__(16) unsigned short BsH[32][BSTR];
    __shared__ __align__(16) unsigned short BsL[32][BSTR];
    __shared__ int rows[128];

    const int bn = blockIdx.x * 128;
    const int bm = blockIdx.y * 128;
    const int t  = threadIdx.x;
    const int lane = t & 31;
    const int w  = t >> 5;
    const int wm = (w >> 2) * 64;
    const int wn = (w & 3) * 32;

    if (t < 128) {
        int m = bm + t;
        rows[t] = x[(m & 63) * S_LEN + (m >> 6)] * HID;
    }
    __syncthreads();

    float acc[4][4][4];
#pragma unroll
    for (int i = 0; i < 4; i++)
#pragma unroll
        for (int j = 0; j < 4; j++)
#pragma unroll
            for (int k = 0; k < 4; k++) acc[i][j][k] = 0.f;

    const int ar = t >> 1, ak = (t & 1) * 16;
    const int bk = t >> 3, bn0 = (t & 7) * 16;

    for (int k0 = 0; k0 < HID; k0 += 32) {
        __syncthreads();
        {
            size_t aoff = (size_t)rows[ar] + k0 + ak;
            *(uint4*)&AsH[ar][ak]     = *(const uint4*)&g_embH[aoff];
            *(uint4*)&AsH[ar][ak + 8] = *(const uint4*)&g_embH[aoff + 8];
            *(uint4*)&AsL[ar][ak]     = *(const uint4*)&g_embL[aoff];
            *(uint4*)&AsL[ar][ak + 8] = *(const uint4*)&g_embL[aoff + 8];
            size_t boff = (size_t)(k0 + bk) * G4 + bn + bn0;
            *(uint4*)&BsH[bk][bn0]     = *(const uint4*)&g_WiH[boff];
            *(uint4*)&BsH[bk][bn0 + 8] = *(const uint4*)&g_WiH[boff + 8];
            *(uint4*)&BsL[bk][bn0]     = *(const uint4*)&g_WiL[boff];
            *(uint4*)&BsL[bk][bn0 + 8] = *(const uint4*)&g_WiL[boff + 8];
        }
        __syncthreads();

#pragma unroll
        for (int k16 = 0; k16 < 2; k16++) {
            uint32_t bH[4][2], bL[4][2];
#pragma unroll
            for (int p = 0; p < 2; p++) {
                int krow = k16 * 16 + (lane & 15);
                int ncol = wn + p * 16 + (lane >> 4) * 8;
                uint32_t r0, r1, r2, r3;
                ldsm_x4t(smem_u32(&BsH[krow][ncol]), r0, r1, r2, r3);
                bH[p * 2][0] = r0; bH[p * 2][1] = r1;
                bH[p * 2 + 1][0] = r2; bH[p * 2 + 1][1] = r3;
                ldsm_x4t(smem_u32(&BsL[krow][ncol]), r0, r1, r2, r3);
                bL[p * 2][0] = r0; bL[p * 2][1] = r1;
                bL[p * 2 + 1][0] = r2; bL[p * 2 + 1][1] = r3;
            }
#pragma unroll
            for (int mf = 0; mf < 4; mf++) {
                int arow = wm + mf * 16 + (lane & 15);
                int acol = k16 * 16 + (lane >> 4) * 8;
                uint32_t aH[4], aL[4];
                ldsm_x4(smem_u32(&AsH[arow][acol]), aH[0], aH[1], aH[2], aH[3]);
                ldsm_x4(smem_u32(&AsL[arow][acol]), aL[0], aL[1], aL[2], aL[3]);
#pragma unroll
                for (int nf = 0; nf < 4; nf++) {
                    mma16816(acc[mf][nf], aH, bH[nf]);
                    mma16816(acc[mf][nf], aH, bL[nf]);
                    mma16816(acc[mf][nf], aL, bH[nf]);
                }
            }
        }
    }
#pragma unroll
    for (int mf = 0; mf < 4; mf++) {
        int gm = bm + wm + mf * 16 + (lane >> 2);
#pragma unroll
        for (int nf = 0; nf < 4; nf++) {
            int gn = bn + wn + nf * 8 + 2 * (lane & 3);
            *(float2*)&g_gx[(size_t)gm * G4 + gn] =
                make_float2(acc[mf][nf][0], acc[mf][nf][1]);
            *(float2*)&g_gx[(size_t)(gm + 8) * G4 + gn] =
                make_float2(acc[mf][nf][2], acc[mf][nf][3]);
        }
    }
}

// ---------------- grid barrier (flat, proven) --------------------------------
__device__ __forceinline__ void grid_barrier(unsigned epoch) {
    __syncthreads();
    if (threadIdx.x == 0) {
        __threadfence();
        unsigned prev = atomicAdd(&g_arrive, 1u);
        if (prev + 1u == (unsigned)NBLK * epoch) {
            atomicExch(&g_release, epoch);
        } else {
            unsigned r;
            do {
                asm volatile("ld.acquire.gpu.u32 %0, [%1];"
                             : "=r"(r) : "l"(&g_release) : "memory");
            } while (r < epoch);
        }
    }
    __syncthreads();
}

// ---------------- persistent scan: hi-only h + c8-pipelined A prefetch -------
#define WHF_BYTES 131072
#define GSM_STR 34
#define SCAN_SMEM (WHF_BYTES + 34816)

__global__ __launch_bounds__(256, 1) void scan_kernel(const float* __restrict__ Wh,
                                                      const float* __restrict__ bh) {
    extern __shared__ char smraw[];
    uint4* WhF = (uint4*)smraw;                                   // [64][4][32]
    float* gsm = (float*)(smraw + WHF_BYTES);                     // [4][64][34]
    __shared__ float bsm[4][UPB];
    __shared__ float csm[64][UPB];

    const int t = threadIdx.x, lane = t & 31, w = t >> 5;
    const int mg = w & 1, ks = w >> 1;        // 2 m-groups x 4 k-splits
    const int j0 = blockIdx.x * UPB;

    // ---- preload Wh slice into fragment-ordered SMEM (once); temp in gsm ----
    __nv_bfloat16* tileH = (__nv_bfloat16*)gsm;         // [128][40]
    __nv_bfloat16* tileL = tileH + 128 * 40;
    for (int kc = 0; kc < 8; kc++) {
        __syncthreads();
#pragma unroll
        for (int i = 0; i < 16; i++) {
            int idx = i * 256 + t;
            int kl = idx >> 5, cc = idx & 31;
            float v = Wh[(size_t)(kc * 128 + kl) * G4 + (cc >> 3) * HID + j0 + (cc & 7)];
            __nv_bfloat16 hi = __float2bfloat16(v);
            __nv_bfloat16 lo = __float2bfloat16(v - __bfloat162float(hi));
            tileH[kl * 40 + cc] = hi;
            tileL[kl * 40 + cc] = lo;
        }
        __syncthreads();
        {
            int krow = w * 16 + (lane & 15);
#pragma unroll
            for (int p = 0; p < 2; p++) {
                int ncol = p * 16 + (lane >> 4) * 8;
                uint32_t h0, h1, h2, h3, l0, l1, l2, l3;
                ldsm_x4t(smem_u32(&tileH[krow * 40 + ncol]), h0, h1, h2, h3);
                ldsm_x4t(smem_u32(&tileL[krow * 40 + ncol]), l0, l1, l2, l3);
                WhF[((kc * 8 + w) * 4 + p * 2 + 0) * 32 + lane] = make_uint4(h0, h1, l0, l1);
                WhF[((kc * 8 + w) * 4 + p * 2 + 1) * 32 + lane] = make_uint4(h2, h3, l2, l3);
            }
        }
    }
    if (t < 32) bsm[t >> 3][t & 7] = bh[(t >> 3) * HID + j0 + (t & 7)];
    for (int e = t; e < 512; e += 256) csm[e >> 3][e & 7] = 0.f;
    grid_barrier(1u);

    // pointwise fragment-store indices
    const int pw_u  = t & 7;
    const int pw_j  = j0 + pw_u;
    const int pw_ct = pw_j >> 4;
    const int pw_ci = pw_j & 15;

    // ---- 512 steps ----
    for (int s = 0; s < S_LEN; ++s) {
        float gxv[2][4];
#pragma unroll
        for (int e2 = 0; e2 < 2; e2++) {
            int e = t + e2 * 256, b = e >> 3;
            const float* gx = &g_gx[((size_t)s * B_SZ + b) * G4 + pw_j];
            gxv[e2][0] = gx[0];
            gxv[e2][1] = gx[HID];
            gxv[e2][2] = gx[2 * HID];
            gxv[e2][3] = gx[3 * HID];
        }

        float acc[2][4][4];
#pragma unroll
        for (int mi = 0; mi < 2; mi++)
#pragma unroll
            for (int g = 0; g < 4; g++)
#pragma unroll
                for (int r = 0; r < 4; r++) acc[mi][g][r] = 0.f;

        const uint4* fragR = &g_hfrag[s & 1][0];

        // prologue: prefetch c8=0's A fragments (4 x uint4)
        uint4 aN[2][2];
#pragma unroll
        for (int kk = 0; kk < 2; kk++)
#pragma unroll
            for (int mi = 0; mi < 2; mi++)
                aN[kk][mi] = fragR[((size_t)(2 * mg + mi) * 64 + (ks * 2 + kk)) * 32 + lane];

#pragma unroll 1
        for (int c8 = 0; c8 < 8; c8++) {
            uint4 aC[2][2];
#pragma unroll
            for (int kk = 0; kk < 2; kk++)
#pragma unroll
                for (int mi = 0; mi < 2; mi++) aC[kk][mi] = aN[kk][mi];
            if (c8 < 7) {
#pragma unroll
                for (int kk = 0; kk < 2; kk++)
#pragma unroll
                    for (int mi = 0; mi < 2; mi++)
                        aN[kk][mi] = fragR[((size_t)(2 * mg + mi) * 64 +
                                            ((c8 + 1) * 8 + ks * 2 + kk)) * 32 + lane];
            }
#pragma unroll
            for (int kk = 0; kk < 2; kk++) {
                const int kl = c8 * 8 + ks * 2 + kk;
                uint32_t bhf[4][2], blf[4][2];
#pragma unroll
                for (int g = 0; g < 4; g++) {
                    uint4 f = WhF[((size_t)kl * 4 + g) * 32 + lane];
                    bhf[g][0] = f.x; bhf[g][1] = f.y;
                    blf[g][0] = f.z; blf[g][1] = f.w;
                }
#pragma unroll
                for (int mi = 0; mi < 2; mi++) {
                    uint32_t aH[4] = { aC[kk][mi].x, aC[kk][mi].y,
                                       aC[kk][mi].z, aC[kk][mi].w };
#pragma unroll
                    for (int g = 0; g < 4; g++) {
                        mma16816(acc[mi][g], aH, bhf[g]);
                        mma16816(acc[mi][g], aH, blf[g]);
                    }
                }
            }
        }
        __syncthreads();   // gsm free
#pragma unroll
        for (int mi = 0; mi < 2; mi++)
#pragma unroll
            for (int g = 0; g < 4; g++) {
                int m = mg * 32 + mi * 16 + (lane >> 2);
                int n = g * 8 + (lane & 3) * 2;
                *(float2*)&gsm[(ks * 64 + m) * GSM_STR + n] =
                    make_float2(acc[mi][g][0], acc[mi][g][1]);
                *(float2*)&gsm[(ks * 64 + m + 8) * GSM_STR + n] =
                    make_float2(acc[mi][g][2], acc[mi][g][3]);
            }
        __syncthreads();

        // pointwise
        unsigned short* fragW = (unsigned short*)&g_hfrag[(s + 1) & 1][0];
#pragma unroll
        for (int e2 = 0; e2 < 2; e2++) {
            int e = t + e2 * 256, b = e >> 3;
            int u = pw_u, j = pw_j;
            float gi = gxv[e2][0] + bsm[0][u];
            float gf = gxv[e2][1] + bsm[1][u];
            float gv = gxv[e2][2] + bsm[2][u];
            float go = gxv[e2][3] + bsm[3][u];
#pragma unroll
            for (int p = 0; p < 4; p++) {
                const float* gr = &gsm[(p * 64 + b) * GSM_STR];
                gi += gr[u];
                gf += gr[8 + u];
                gv += gr[16 + u];
                go += gr[24 + u];
            }
            gi = 1.f / (1.f + expf(-gi));
            gf = 1.f / (1.f + expf(-gf));
            gv = tanhf(gv);
            go = 1.f / (1.f + expf(-go));
            float c = gf * csm[b][u] + gi * gv;
            float h = go * tanhf(c);
            csm[b][u] = c;
            __nv_bfloat16 hh = __float2bfloat16(h);
            int ri = b & 15;
            int lane_w = (ri & 7) * 4 + ((pw_ci & 7) >> 1);
            int comp = ((ri >> 3) & 1) | (((pw_ci >> 3) & 1) << 1);
            size_t off16 = ((((size_t)(b >> 4) * 64 + pw_ct) * 32 + lane_w) * 4 + comp) * 2
                           + (pw_ci & 1);
            fragW[off16] = __bfloat16_as_ushort(hh);
            g_hs[((size_t)b * S_LEN + s) * HID + j] = h;
        }
        grid_barrier((unsigned)(s + 2));
    }
}

// ---------------- phase 3: logits = hs @ Wo + bo (bf16-split HMMA) -----------
__global__ __launch_bounds__(256) void gemm_logits(const float* __restrict__ Wo,
                                                   const float* __restrict__ bo,
                                                   float* __restrict__ out) {
    __shared__ __align__(16) unsigned short AsH[128][ASTR];
    __shared__ __align__(16) unsigned short AsL[128][ASTR];
    __shared__ __align__(16) unsigned short BsH[32][BSTR];
    __shared__ __align__(16) unsigned short BsL[32][BSTR];

    const int bm = blockIdx.x * 128;
    const int t  = threadIdx.x;
    const int lane = t & 31;
    const int w  = t >> 5;
    const int wm = (w >> 2) * 64;
    const int wn = (w & 3) * 32;

    float acc[4][4][4];
#pragma unroll
    for (int i = 0; i < 4; i++)
#pragma unroll
        for (int j = 0; j < 4; j++)
#pragma unroll
            for (int k = 0; k < 4; k++) acc[i][j][k] = 0.f;

    const int ar = t >> 1, ak = (t & 1) * 16;
    const int bk = t >> 3, bn0 = (t & 7) * 16;

    for (int k0 = 0; k0 < HID; k0 += 32) {
        __syncthreads();
#pragma unroll
        for (int i = 0; i < 4; i++) {
            float4 v = *(const float4*)&g_hs[(size_t)(bm + ar) * HID + k0 + ak + i * 4];
            uint32_t h0, h1, l0, l1; split4(v, h0, h1, l0, l1);
            *(uint2*)&AsH[ar][ak + i * 4] = make_uint2(h0, h1);
            *(uint2*)&AsL[ar][ak + i * 4] = make_uint2(l0, l1);
        }
        {
            uint32_t hh[8], ll[8];
#pragma unroll
            for (int i = 0; i < 4; i++) {
                float4 v = *(const float4*)&Wo[(size_t)(k0 + bk) * NACT + bn0 + i * 4];
                split4(v, hh[i * 2], hh[i * 2 + 1], ll[i * 2], ll[i * 2 + 1]);
            }
            *(uint4*)&BsH[bk][bn0]     = make_uint4(hh[0], hh[1], hh[2], hh[3]);
            *(uint4*)&BsH[bk][bn0 + 8] = make_uint4(hh[4], hh[5], hh[6], hh[7]);
            *(uint4*)&BsL[bk][bn0]     = make_uint4(ll[0], ll[1], ll[2], ll[3]);
            *(uint4*)&BsL[bk][bn0 + 8] = make_uint4(ll[4], ll[5], ll[6], ll[7]);
        }
        __syncthreads();

#pragma unroll
        for (int k16 = 0; k16 < 2; k16++) {
            uint32_t bH[4][2], bL[4][2];
#pragma unroll
            for (int p = 0; p < 2; p++) {
                int krow = k16 * 16 + (lane & 15);
                int ncol = wn + p * 16 + (lane >> 4) * 8;
                uint32_t r0, r1, r2, r3;
                ldsm_x4t(smem_u32(&BsH[krow][ncol]), r0, r1, r2, r3);
                bH[p * 2][0] = r0; bH[p * 2][1] = r1;
                bH[p * 2 + 1][0] = r2; bH[p * 2 + 1][1] = r3;
                ldsm_x4t(smem_u32(&BsL[krow][ncol]), r0, r1, r2, r3);
                bL[p * 2][0] = r0; bL[p * 2][1] = r1;
                bL[p * 2 + 1][0] = r2; bL[p * 2 + 1][1] = r3;
            }
#pragma unroll
            for (int mf = 0; mf < 4; mf++) {
                int arow = wm + mf * 16 + (lane & 15);
                int acol = k16 * 16 + (lane >> 4) * 8;
                uint32_t aH[4], aL[4];
                ldsm_x4(smem_u32(&AsH[arow][acol]), aH[0], aH[1], aH[2], aH[3]);
                ldsm_x4(smem_u32(&AsL[arow][acol]), aL[0], aL[1], aL[2], aL[3]);
#pragma unroll
                for (int nf = 0; nf < 4; nf++) {
                    mma16816(acc[mf][nf], aH, bH[nf]);
                    mma16816(acc[mf][nf], aH, bL[nf]);
                    mma16816(acc[mf][nf], aL, bH[nf]);
                }
            }
        }
    }
#pragma unroll
    for (int mf = 0; mf < 4; mf++) {
        int gm = bm + wm + mf * 16 + (lane >> 2);
#pragma unroll
        for (int nf = 0; nf < 4; nf++) {
            int gn = wn + nf * 8 + 2 * (lane & 3);
            float b0 = bo[gn], b1 = bo[gn + 1];
            *(float2*)&out[(size_t)gm * NACT + gn] =
                make_float2(acc[mf][nf][0] + b0, acc[mf][nf][1] + b1);
            *(float2*)&out[(size_t)(gm + 8) * NACT + gn] =
                make_float2(acc[mf][nf][2] + b0, acc[mf][nf][3] + b1);
        }
    }
}

// ---------------- launch -----------------------------------------------------
extern "C" void kernel_launch(void* const* d_in, const int* in_sizes, int n_in,
                              void* d_out, int out_size) {
    const float* embed = (const float*)d_in[0];
    const float* Wi    = (const float*)d_in[1];
    const float* Wh    = (const float*)d_in[2];
    const float* bh    = (const float*)d_in[3];
    const float* Wo    = (const float*)d_in[4];
    const float* bo    = (const float*)d_in[5];
    const int*   x     = (const int*)d_in[6];
    float* out = (float*)d_out;

    int has_dummy = (out_size == B_SZ * S_LEN * (NACT + 2)) ? 1 : 0;
    int logits_off = has_dummy ? B_SZ * S_LEN : 0;

    static int smem_set = 0;
    if (!smem_set) {
        cudaFuncSetAttribute(scan_kernel,
                             cudaFuncAttributeMaxDynamicSharedMemorySize, SCAN_SMEM);
        smem_set = 1;
    }

    __nv_bfloat16 *eH, *eL, *wH, *wL;
    cudaGetSymbolAddress((void**)&eH, g_embH);
    cudaGetSymbolAddress((void**)&eL, g_embL);
    cudaGetSymbolAddress((void**)&wH, g_WiH);
    cudaGetSymbolAddress((void**)&wL, g_WiL);

    init_kernel<<<256, 256>>>(out, has_dummy);
    prep_split<<<(VOCAB * HID) / 1024, 256>>>(embed, eH, eL);
    prep_split<<<(HID * G4) / 1024, 256>>>(Wi, wH, wL);
    gemm_gx<<<dim3(G4 / 128, (S_LEN * B_SZ) / 128), 256>>>(x);
    scan_kernel<<<NBLK, 256, SCAN_SMEM>>>(Wh, bh);
    gemm_logits<<<(S_LEN * B_SZ) / 128, 256>>>(Wo, bo, out + logits_off);
}